// round 6
// baseline (speedup 1.0000x reference)
#include <cuda_runtime.h>
#include <cuda_bf16.h>
#include <math.h>
#include <stdint.h>

#define BSZ 2
#define LSEQ 2048
#define DMODEL 1024
#define DINNER 2048
#define NSTATE 16
#define ROWS (BSZ*LSEQ)   /* 4096 */

/* ------------------------------------------------------------------ */
/* Scratch (bf16 intermediates; every bf16 path is averaged by a      */
/* >=2048-length reduction before the output)                         */
/* ------------------------------------------------------------------ */
__device__ __nv_bfloat16 g_hb [(size_t)ROWS*DMODEL];    /* post-LN          */
__device__ __nv_bfloat16 g_xgb[(size_t)ROWS*2*DINNER];  /* xs_raw | silu(gate) */
__device__ __nv_bfloat16 g_xsb[(size_t)ROWS*DINNER];    /* conv+silu        */
__device__ float g_delta[ROWS];
__device__ float g_dA  [(size_t)ROWS*NSTATE];
__device__ float g_Bx  [(size_t)ROWS*NSTATE];
__device__ float g_hs  [(size_t)ROWS*NSTATE];
__device__ __nv_bfloat16 g_yb [(size_t)ROWS*DINNER];    /* pre-W_out        */
__device__ __nv_bfloat16 g_wt [(size_t)4096*2048];      /* transposed W     */

__device__ __forceinline__ uint32_t smem_u32(const void* p) {
    uint32_t a;
    asm("{ .reg .u64 t; cvta.to.shared.u64 t, %1; cvt.u32.u64 %0, t; }" : "=r"(a) : "l"(p));
    return a;
}

/* ------------------------------------------------------------------ */
/* LayerNorm (+ zero delta): one block per row of 1024                */
/* ------------------------------------------------------------------ */
__global__ void ln_kernel(const float* __restrict__ x,
                          const float* __restrict__ gamma,
                          const float* __restrict__ beta)
{
    int row = blockIdx.x;
    int tx  = threadIdx.x;                       /* 256 threads */
    if (tx == 0) g_delta[row] = 0.f;
    const float4* xr = (const float4*)(x + (size_t)row*DMODEL);
    float4 v = xr[tx];
    float s  = v.x + v.y + v.z + v.w;
    float ss = v.x*v.x + v.y*v.y + v.z*v.z + v.w*v.w;
    #pragma unroll
    for (int o = 16; o; o >>= 1) {
        s  += __shfl_down_sync(0xffffffffu, s,  o);
        ss += __shfl_down_sync(0xffffffffu, ss, o);
    }
    __shared__ float sh[8], sh2[8];
    int w = tx >> 5, l = tx & 31;
    if (l == 0) { sh[w] = s; sh2[w] = ss; }
    __syncthreads();
    if (tx == 0) {
        float S = 0.f, SS = 0.f;
        #pragma unroll
        for (int i = 0; i < 8; i++) { S += sh[i]; SS += sh2[i]; }
        sh[0]  = S  * (1.0f/DMODEL);
        sh2[0] = SS * (1.0f/DMODEL);
    }
    __syncthreads();
    float mean = sh[0];
    float var  = sh2[0] - mean*mean;
    float r    = rsqrtf(var + 1e-5f);
    float4 gg = ((const float4*)gamma)[tx];
    float4 bb = ((const float4*)beta )[tx];
    __nv_bfloat162 lo = __floats2bfloat162_rn((v.x - mean)*r*gg.x + bb.x,
                                              (v.y - mean)*r*gg.y + bb.y);
    __nv_bfloat162 hi = __floats2bfloat162_rn((v.z - mean)*r*gg.z + bb.z,
                                              (v.w - mean)*r*gg.w + bb.w);
    *(uint2*)(g_hb + (size_t)row*DMODEL + tx*4) =
        make_uint2(*(uint32_t*)&lo, *(uint32_t*)&hi);
}

/* ------------------------------------------------------------------ */
/* Transpose weight [K,N] fp32 -> [N,K] bf16.                         */
/* ------------------------------------------------------------------ */
__global__ void transpose_bf16_kernel(const float* __restrict__ W,
                                      __nv_bfloat16* __restrict__ Wt, int K, int N)
{
    __shared__ float tile[32][33];
    int n0 = blockIdx.x*32, k0 = blockIdx.y*32;
    int tx = threadIdx.x, ty = threadIdx.y;
    #pragma unroll
    for (int i = 0; i < 32; i += 8)
        tile[ty+i][tx] = W[(size_t)(k0+ty+i)*N + n0+tx];
    __syncthreads();
    #pragma unroll
    for (int i = 0; i < 32; i += 8)
        Wt[(size_t)(n0+ty+i)*K + k0+tx] = __float2bfloat16_rn(tile[tx][ty+i]);
}

/* ------------------------------------------------------------------ */
/* bf16 mma.sync GEMM, cp.async 4-stage pipeline, BN templated.       */
/* MODE 0: bf16 store (silu applied when col0 >= gate_from)           */
/* MODE 1: rowsum += softplus(acc+bias)                               */
/* MODE 2: fp32 store C = acc + resid                                 */
/* ------------------------------------------------------------------ */
#define SROW 80
#define NSTG 4

#define CPASYNC16(dst, src) \
    asm volatile("cp.async.cg.shared.global [%0], [%1], 16;" :: "r"(dst), "l"(src))
#define CP_COMMIT() asm volatile("cp.async.commit_group;" ::: "memory")
#define CP_WAIT2()  asm volatile("cp.async.wait_group 2;" ::: "memory")

#define LDSM4(r0,r1,r2,r3, addr) \
    asm volatile("ldmatrix.sync.aligned.m8n8.x4.shared.b16 {%0,%1,%2,%3}, [%4];" \
        : "=r"(r0),"=r"(r1),"=r"(r2),"=r"(r3) : "r"(addr))

#define MMA_BF16(c, a, b0v, b1v) \
    asm volatile("mma.sync.aligned.m16n8k16.row.col.f32.bf16.bf16.f32 " \
        "{%0,%1,%2,%3},{%4,%5,%6,%7},{%8,%9},{%0,%1,%2,%3};" \
        : "+f"((c)[0]),"+f"((c)[1]),"+f"((c)[2]),"+f"((c)[3]) \
        : "r"((a)[0]),"r"((a)[1]),"r"((a)[2]),"r"((a)[3]), "r"(b0v),"r"(b1v))

template<int BN>
__device__ __forceinline__ void stage_issue(uint32_t sbase, int stage,
                                            const __nv_bfloat16* Ab,
                                            const __nv_bfloat16* Bb,
                                            int Kd, int c, int tid)
{
    const int STAGEB = (128 + BN) * SROW;
    uint32_t sA = sbase + stage*STAGEB;
    uint32_t sB = sA + 128*SROW;
    int seg = tid & 3;
    int row = tid >> 2;                 /* 0..63 */
    #pragma unroll
    for (int i = 0; i < 2; i++) {
        int r = row + 64*i;
        CPASYNC16(sA + (uint32_t)(r*SROW + seg*16),
                  Ab + (size_t)r*Kd + c*32 + seg*8);
    }
    #pragma unroll
    for (int i = 0; i < BN/64; i++) {
        int r = row + 64*i;
        CPASYNC16(sB + (uint32_t)(r*SROW + seg*16),
                  Bb + (size_t)r*Kd + c*32 + seg*8);
    }
}

template<int MODE, int BN>
__global__ __launch_bounds__(256, 2)
void mm_gemm_kernel(const __nv_bfloat16* __restrict__ A,
                    const __nv_bfloat16* __restrict__ Bt,
                    void* __restrict__ Cv, int M, int N, int Kd,
                    const float* __restrict__ bias,
                    float* __restrict__ rowsum,
                    const float* __restrict__ resid,
                    int gate_from)
{
    extern __shared__ __align__(16) unsigned char gsm[];
    uint32_t sbase = smem_u32(gsm);
    const int STAGEB = (128 + BN) * SROW;
    const int NT = BN/32;              /* n-tiles of 8 per warp */

    int tid  = threadIdx.x;
    int wid  = tid >> 5;
    int lane = tid & 31;
    int g    = lane >> 2;
    int q    = lane & 3;
    int mwb  = (wid & 1) * 64;
    int nwb  = (wid >> 1) * (BN/4);
    int row0 = blockIdx.y * 128;
    int col0 = blockIdx.x * BN;

    const __nv_bfloat16* Ab = A  + (size_t)row0*Kd;
    const __nv_bfloat16* Bb = Bt + (size_t)col0*Kd;

    int r8 = lane & 7;
    uint32_t laneA = (uint32_t)((r8 + ((lane>>3)&1)*8)*SROW + ((lane>>4)&1)*16);
    uint32_t laneB = (uint32_t)((r8 + ((lane>>4)&1)*8)*SROW + ((lane>>3)&1)*16);

    float acc[4][NT][4];
    #pragma unroll
    for (int mt = 0; mt < 4; mt++)
        #pragma unroll
        for (int nt = 0; nt < NT; nt++)
            #pragma unroll
            for (int j = 0; j < 4; j++) acc[mt][nt][j] = 0.f;

    const int nch = Kd >> 5;

    stage_issue<BN>(sbase, 0, Ab, Bb, Kd, 0, tid); CP_COMMIT();
    stage_issue<BN>(sbase, 1, Ab, Bb, Kd, 1, tid); CP_COMMIT();
    stage_issue<BN>(sbase, 2, Ab, Bb, Kd, 2, tid); CP_COMMIT();

    for (int c = 0; c < nch; c++) {
        CP_WAIT2();
        __syncthreads();
        if (c + 3 < nch)
            stage_issue<BN>(sbase, (c+3)%NSTG, Ab, Bb, Kd, c+3, tid);
        CP_COMMIT();

        uint32_t aBase = sbase + (c%NSTG)*STAGEB            + laneA;
        uint32_t bBase = sbase + (c%NSTG)*STAGEB + 128*SROW + laneB;
        #pragma unroll
        for (int ks = 0; ks < 2; ks++) {
            uint32_t af[4][4], bf4[NT/2][4];
            #pragma unroll
            for (int mt = 0; mt < 4; mt++)
                LDSM4(af[mt][0], af[mt][1], af[mt][2], af[mt][3],
                      aBase + (uint32_t)((mwb + mt*16)*SROW + ks*32));
            #pragma unroll
            for (int np = 0; np < NT/2; np++)
                LDSM4(bf4[np][0], bf4[np][1], bf4[np][2], bf4[np][3],
                      bBase + (uint32_t)((nwb + np*16)*SROW + ks*32));
            #pragma unroll
            for (int mt = 0; mt < 4; mt++)
                #pragma unroll
                for (int nt = 0; nt < NT; nt++)
                    MMA_BF16(acc[mt][nt], af[mt],
                             bf4[nt>>1][(nt&1)*2], bf4[nt>>1][(nt&1)*2+1]);
        }
    }
    __syncthreads();

    /* --------------------------- epilogue -------------------------- */
    if (MODE == 1) {
        float part[4][2];
        #pragma unroll
        for (int mt = 0; mt < 4; mt++) {
            float s0 = 0.f, s1 = 0.f;
            #pragma unroll
            for (int nt = 0; nt < NT; nt++) {
                int colb = col0 + nwb + nt*8 + 2*q;
                float b0 = bias[colb], b1 = bias[colb+1];
                float z;
                z = acc[mt][nt][0] + b0; s0 += (z > 20.f) ? z : log1pf(__expf(z));
                z = acc[mt][nt][1] + b1; s0 += (z > 20.f) ? z : log1pf(__expf(z));
                z = acc[mt][nt][2] + b0; s1 += (z > 20.f) ? z : log1pf(__expf(z));
                z = acc[mt][nt][3] + b1; s1 += (z > 20.f) ? z : log1pf(__expf(z));
            }
            part[mt][0] = s0; part[mt][1] = s1;
        }
        float* red = (float*)gsm;
        if (tid < 128) red[tid] = 0.f;
        __syncthreads();
        #pragma unroll
        for (int mt = 0; mt < 4; mt++) {
            atomicAdd(&red[mwb + mt*16 + g    ], part[mt][0]);
            atomicAdd(&red[mwb + mt*16 + g + 8], part[mt][1]);
        }
        __syncthreads();
        if (tid < 128)
            atomicAdd(&rowsum[row0 + tid], red[tid]);
    } else if (MODE == 0) {
        __nv_bfloat16* Cb = (__nv_bfloat16*)Cv;
        bool gate = (col0 >= gate_from);
        #pragma unroll
        for (int mt = 0; mt < 4; mt++) {
            int r0 = row0 + mwb + mt*16 + g;
            #pragma unroll
            for (int nt = 0; nt < NT; nt++) {
                int col = col0 + nwb + nt*8 + 2*q;
                float a0 = acc[mt][nt][0], a1 = acc[mt][nt][1];
                float a2 = acc[mt][nt][2], a3 = acc[mt][nt][3];
                if (gate) {
                    a0 = a0 / (1.f + __expf(-a0));
                    a1 = a1 / (1.f + __expf(-a1));
                    a2 = a2 / (1.f + __expf(-a2));
                    a3 = a3 / (1.f + __expf(-a3));
                }
                *(__nv_bfloat162*)(Cb + (size_t)r0*N + col) =
                    __floats2bfloat162_rn(a0, a1);
                *(__nv_bfloat162*)(Cb + (size_t)(r0+8)*N + col) =
                    __floats2bfloat162_rn(a2, a3);
            }
        }
    } else {
        float* C = (float*)Cv;
        #pragma unroll
        for (int mt = 0; mt < 4; mt++) {
            int r0 = row0 + mwb + mt*16 + g;
            #pragma unroll
            for (int nt = 0; nt < NT; nt++) {
                int col = col0 + nwb + nt*8 + 2*q;
                float2 o0 = make_float2(acc[mt][nt][0], acc[mt][nt][1]);
                float2 o1 = make_float2(acc[mt][nt][2], acc[mt][nt][3]);
                float2 rr0 = *(const float2*)(resid + (size_t)r0*N + col);
                float2 rr1 = *(const float2*)(resid + (size_t)(r0+8)*N + col);
                o0.x += rr0.x; o0.y += rr0.y;
                o1.x += rr1.x; o1.y += rr1.y;
                *(float2*)(C + (size_t)r0*N + col)     = o0;
                *(float2*)(C + (size_t)(r0+8)*N + col) = o1;
            }
        }
    }
}

/* ------------------------------------------------------------------ */
/* Depthwise causal conv (K=4) + bias + SiLU. bf16 in/out, 2 ch/thr.  */
/* ------------------------------------------------------------------ */
#define CONV_CH 64
__global__ void conv_silu_kernel(const float* __restrict__ conv_w,
                                 const float* __restrict__ conv_b)
{
    int p  = blockIdx.x*256 + threadIdx.x;    /* pair 0..1023 */
    int d  = p*2;
    int b  = blockIdx.z;
    int l0 = blockIdx.y * CONV_CH;

    float4 wA = *(const float4*)(conv_w + d*4);
    float4 wB = *(const float4*)(conv_w + (d+1)*4);
    float cbA = conv_b[d], cbB = conv_b[d+1];

    const __nv_bfloat16* xg = g_xgb;
    float p1A=0.f,p2A=0.f,p3A=0.f, p1B=0.f,p2B=0.f,p3B=0.f;
    if (l0 >= 1) { __nv_bfloat162 t = *(const __nv_bfloat162*)(xg + ((size_t)(b*LSEQ+l0-1))*(2*DINNER) + d); p1A=__low2float(t); p1B=__high2float(t); }
    if (l0 >= 2) { __nv_bfloat162 t = *(const __nv_bfloat162*)(xg + ((size_t)(b*LSEQ+l0-2))*(2*DINNER) + d); p2A=__low2float(t); p2B=__high2float(t); }
    if (l0 >= 3) { __nv_bfloat162 t = *(const __nv_bfloat162*)(xg + ((size_t)(b*LSEQ+l0-3))*(2*DINNER) + d); p3A=__low2float(t); p3B=__high2float(t); }

    for (int i = 0; i < CONV_CH; i++) {
        int l = l0 + i;
        __nv_bfloat162 t = *(const __nv_bfloat162*)(xg + ((size_t)(b*LSEQ+l))*(2*DINNER) + d);
        float cA = __low2float(t), cB = __high2float(t);
        float vA = wA.x*p3A + wA.y*p2A + wA.z*p1A + wA.w*cA + cbA;
        float vB = wB.x*p3B + wB.y*p2B + wB.z*p1B + wB.w*cB + cbB;
        float sA = vA / (1.f + __expf(-vA));
        float sB = vB / (1.f + __expf(-vB));
        *(__nv_bfloat162*)(g_xsb + ((size_t)(b*LSEQ+l))*DINNER + d) =
            __floats2bfloat162_rn(sA, sB);
        p3A = p2A; p2A = p1A; p1A = cA;
        p3B = p2B; p2B = p1B; p1B = cB;
    }
}

/* ------------------------------------------------------------------ */
/* Bx + dA: 8 rows per block (one warp per row), bf16 xs.             */
/* ------------------------------------------------------------------ */
__global__ void bxda_kernel(const float* __restrict__ B_mat,
                            const float* __restrict__ A_log)
{
    int row  = blockIdx.x*8 + (threadIdx.x >> 5);
    int lane = threadIdx.x & 31;

    float sums[NSTATE];
    #pragma unroll
    for (int n = 0; n < NSTATE; n++) sums[n] = 0.f;

    const __nv_bfloat16* xr = g_xsb + (size_t)row*DINNER;
    for (int pp = lane; pp < DINNER/2; pp += 32) {
        __nv_bfloat162 t = *(const __nv_bfloat162*)(xr + pp*2);
        float x0 = __low2float(t), x1 = __high2float(t);
        #pragma unroll
        for (int n = 0; n < NSTATE; n++) {
            float2 bm = *(const float2*)(B_mat + (size_t)n*DINNER + pp*2);
            sums[n] += x0*bm.x + x1*bm.y;
        }
    }
    #pragma unroll
    for (int n = 0; n < NSTATE; n++)
        #pragma unroll
        for (int o = 16; o; o >>= 1)
            sums[n] += __shfl_xor_sync(0xffffffffu, sums[n], o);

    if (lane < NSTATE) {
        float delta = g_delta[row] * (1.0f/DINNER);
        float An    = -__expf(A_log[lane]);
        g_Bx[row*NSTATE + lane] = sums[lane] * delta;
        g_dA[row*NSTATE + lane] = __expf(delta * An);
    }
}

/* ------------------------------------------------------------------ */
/* Parallel scan (Hillis-Steele over affine maps)                     */
/* ------------------------------------------------------------------ */
__global__ __launch_bounds__(1024)
void scan_kernel()
{
    __shared__ float Aa[2][LSEQ];
    __shared__ float Bb[2][LSEQ];
    int bn = blockIdx.x;
    int b  = bn >> 4;
    int n  = bn & 15;
    int tid = threadIdx.x;

    for (int l = tid; l < LSEQ; l += 1024) {
        size_t idx = ((size_t)(b*LSEQ + l))*NSTATE + n;
        Aa[0][l] = g_dA[idx];
        Bb[0][l] = g_Bx[idx];
    }
    __syncthreads();
    int src = 0;
    for (int off = 1; off < LSEQ; off <<= 1) {
        int dst = src ^ 1;
        for (int l = tid; l < LSEQ; l += 1024) {
            float a = Aa[src][l], bv = Bb[src][l];
            if (l >= off) {
                float ap = Aa[src][l-off], bp = Bb[src][l-off];
                Aa[dst][l] = a * ap;
                Bb[dst][l] = a * bp + bv;
            } else {
                Aa[dst][l] = a;
                Bb[dst][l] = bv;
            }
        }
        __syncthreads();
        src ^= 1;
    }
    for (int l = tid; l < LSEQ; l += 1024) {
        size_t idx = ((size_t)(b*LSEQ + l))*NSTATE + n;
        g_hs[idx] = Bb[src][l];
    }
}

/* ------------------------------------------------------------------ */
/* y = (hs @ C^T + D*xs) * gate   (gate pre-silu'd), bf16 out.        */
/* ------------------------------------------------------------------ */
__global__ void ymix_kernel(const float* __restrict__ C_mat,
                            const float* __restrict__ D_vec)
{
    int row = blockIdx.x;
    int tx  = threadIdx.x;      /* 256 */
    __shared__ float hrow[NSTATE];
    if (tx < NSTATE) hrow[tx] = g_hs[row*NSTATE + tx];
    __syncthreads();

    for (int pp = tx; pp < DINNER/2; pp += 256) {
        int d = pp*2;
        float acc0 = 0.f, acc1 = 0.f;
        const float4* c0 = (const float4*)(C_mat + (size_t)d*NSTATE);
        const float4* c1 = (const float4*)(C_mat + (size_t)(d+1)*NSTATE);
        #pragma unroll
        for (int qq = 0; qq < 4; qq++) {
            float4 ca = c0[qq], cb = c1[qq];
            acc0 += ca.x*hrow[qq*4+0] + ca.y*hrow[qq*4+1]
                  + ca.z*hrow[qq*4+2] + ca.w*hrow[qq*4+3];
            acc1 += cb.x*hrow[qq*4+0] + cb.y*hrow[qq*4+1]
                  + cb.z*hrow[qq*4+2] + cb.w*hrow[qq*4+3];
        }
        __nv_bfloat162 xt = *(const __nv_bfloat162*)(g_xsb + (size_t)row*DINNER + d);
        __nv_bfloat162 gt = *(const __nv_bfloat162*)(g_xgb + (size_t)row*(2*DINNER) + DINNER + d);
        float2 Dv = *(const float2*)(D_vec + d);
        float y0 = (acc0 + Dv.x*__low2float (xt)) * __low2float (gt);
        float y1 = (acc1 + Dv.y*__high2float(xt)) * __high2float(gt);
        *(__nv_bfloat162*)(g_yb + (size_t)row*DINNER + d) =
            __floats2bfloat162_rn(y0, y1);
    }
}

/* ------------------------------------------------------------------ */
extern "C" void kernel_launch(void* const* d_in, const int* in_sizes, int n_in,
                              void* d_out, int out_size)
{
    const float* x        = (const float*)d_in[0];
    const float* ln_gamma = (const float*)d_in[1];
    const float* ln_beta  = (const float*)d_in[2];
    const float* W_in     = (const float*)d_in[3];
    const float* conv_w   = (const float*)d_in[4];
    const float* conv_b   = (const float*)d_in[5];
    const float* A_log    = (const float*)d_in[6];
    const float* B_mat    = (const float*)d_in[7];
    const float* C_mat    = (const float*)d_in[8];
    const float* D_vec    = (const float*)d_in[9];
    const float* Wd       = (const float*)d_in[10];
    const float* bd       = (const float*)d_in[11];
    const float* W_out    = (const float*)d_in[12];
    float* out = (float*)d_out;

    float *p_delta;
    __nv_bfloat16 *p_hb, *p_xgb, *p_xsb, *p_yb, *p_wt;
    cudaGetSymbolAddress((void**)&p_hb,    g_hb);
    cudaGetSymbolAddress((void**)&p_xgb,   g_xgb);
    cudaGetSymbolAddress((void**)&p_xsb,   g_xsb);
    cudaGetSymbolAddress((void**)&p_delta, g_delta);
    cudaGetSymbolAddress((void**)&p_yb,    g_yb);
    cudaGetSymbolAddress((void**)&p_wt,    g_wt);

    const int SM128 = NSTG*(128+128)*SROW;   /* 81920 */
    const int SM64  = NSTG*(128+ 64)*SROW;   /* 61440 */
    cudaFuncSetAttribute((const void*)mm_gemm_kernel<0,128>,
        cudaFuncAttributeMaxDynamicSharedMemorySize, SM128);
    cudaFuncSetAttribute((const void*)mm_gemm_kernel<1,128>,
        cudaFuncAttributeMaxDynamicSharedMemorySize, SM128);
    cudaFuncSetAttribute((const void*)mm_gemm_kernel<2,64>,
        cudaFuncAttributeMaxDynamicSharedMemorySize, SM64);

    /* 1. LayerNorm (bf16 out) + delta zero */
    ln_kernel<<<ROWS, 256>>>(x, ln_gamma, ln_beta);

    /* 2. W_in^T, then xg = h @ W_in  (gate half gets silu, bf16) */
    transpose_bf16_kernel<<<dim3((2*DINNER)/32, DMODEL/32), dim3(32,8)>>>(
        W_in, p_wt, DMODEL, 2*DINNER);
    mm_gemm_kernel<0,128><<<dim3((2*DINNER)/128, ROWS/128), 256, SM128>>>(
        p_hb, p_wt, p_xgb, ROWS, 2*DINNER, DMODEL,
        nullptr, nullptr, nullptr, DINNER);

    /* 3. depthwise causal conv + SiLU (bf16) */
    conv_silu_kernel<<<dim3(DINNER/512, LSEQ/CONV_CH, BSZ), 256>>>(conv_w, conv_b);

    /* 4. Wd^T, then delta row-sums = sum softplus(xs @ Wd + bd) */
    transpose_bf16_kernel<<<dim3(DINNER/32, DINNER/32), dim3(32,8)>>>(
        Wd, p_wt, DINNER, DINNER);
    mm_gemm_kernel<1,128><<<dim3(DINNER/128, ROWS/128), 256, SM128>>>(
        p_xsb, p_wt, nullptr, ROWS, DINNER, DINNER,
        bd, p_delta, nullptr, 1<<30);

    /* 5. Bx, dA */
    bxda_kernel<<<ROWS/8, 256>>>(B_mat, A_log);

    /* 6. scan over L */
    scan_kernel<<<BSZ*NSTATE, 1024>>>();

    /* 7. y = (hs @ C^T + D*xs) * gate  (bf16 out) */
    ymix_kernel<<<ROWS, 256>>>(C_mat, D_vec);

    /* 8. W_out^T, then out = y @ W_out + x  (BN=64 tiles: 512 CTAs) */
    transpose_bf16_kernel<<<dim3(DMODEL/32, DINNER/32), dim3(32,8)>>>(
        W_out, p_wt, DINNER, DMODEL);
    mm_gemm_kernel<2,64><<<dim3(DMODEL/64, ROWS/128), 256, SM64>>>(
        p_yb, p_wt, out, ROWS, DMODEL, DINNER,
        nullptr, nullptr, x, 1<<30);
}

// round 7
// speedup vs baseline: 1.0544x; 1.0544x over previous
#include <cuda_runtime.h>
#include <cuda_bf16.h>
#include <math.h>
#include <stdint.h>

#define BSZ 2
#define LSEQ 2048
#define DMODEL 1024
#define DINNER 2048
#define NSTATE 16
#define ROWS (BSZ*LSEQ)   /* 4096 */

/* ------------------------------------------------------------------ */
/* Scratch (bf16 intermediates; every bf16 path feeds a >=2048-length */
/* averaged reduction before the output)                              */
/* ------------------------------------------------------------------ */
__device__ __nv_bfloat16 g_hb [(size_t)ROWS*DMODEL];    /* post-LN          */
__device__ __nv_bfloat16 g_xgb[(size_t)ROWS*2*DINNER];  /* xs_raw | silu(gate) */
__device__ __nv_bfloat16 g_xsb[(size_t)ROWS*DINNER];    /* conv+silu        */
__device__ float g_delta[ROWS];
__device__ float g_dA  [(size_t)ROWS*NSTATE];
__device__ float g_Bx  [(size_t)ROWS*NSTATE];
__device__ float g_hs  [(size_t)ROWS*NSTATE];
__device__ __nv_bfloat16 g_yb [(size_t)ROWS*DINNER];    /* pre-W_out        */
__device__ __nv_bfloat16 g_wt [(size_t)4096*2048];      /* transposed W     */

__device__ __forceinline__ uint32_t smem_u32(const void* p) {
    uint32_t a;
    asm("{ .reg .u64 t; cvta.to.shared.u64 t, %1; cvt.u32.u64 %0, t; }" : "=r"(a) : "l"(p));
    return a;
}

/* ------------------------------------------------------------------ */
/* LayerNorm (+ zero delta): one block per row of 1024                */
/* ------------------------------------------------------------------ */
__global__ void ln_kernel(const float* __restrict__ x,
                          const float* __restrict__ gamma,
                          const float* __restrict__ beta)
{
    int row = blockIdx.x;
    int tx  = threadIdx.x;                       /* 256 threads */
    if (tx == 0) g_delta[row] = 0.f;
    const float4* xr = (const float4*)(x + (size_t)row*DMODEL);
    float4 v = xr[tx];
    float s  = v.x + v.y + v.z + v.w;
    float ss = v.x*v.x + v.y*v.y + v.z*v.z + v.w*v.w;
    #pragma unroll
    for (int o = 16; o; o >>= 1) {
        s  += __shfl_down_sync(0xffffffffu, s,  o);
        ss += __shfl_down_sync(0xffffffffu, ss, o);
    }
    __shared__ float sh[8], sh2[8];
    int w = tx >> 5, l = tx & 31;
    if (l == 0) { sh[w] = s; sh2[w] = ss; }
    __syncthreads();
    if (tx == 0) {
        float S = 0.f, SS = 0.f;
        #pragma unroll
        for (int i = 0; i < 8; i++) { S += sh[i]; SS += sh2[i]; }
        sh[0]  = S  * (1.0f/DMODEL);
        sh2[0] = SS * (1.0f/DMODEL);
    }
    __syncthreads();
    float mean = sh[0];
    float var  = sh2[0] - mean*mean;
    float r    = rsqrtf(var + 1e-5f);
    float4 gg = ((const float4*)gamma)[tx];
    float4 bb = ((const float4*)beta )[tx];
    __nv_bfloat162 lo = __floats2bfloat162_rn((v.x - mean)*r*gg.x + bb.x,
                                              (v.y - mean)*r*gg.y + bb.y);
    __nv_bfloat162 hi = __floats2bfloat162_rn((v.z - mean)*r*gg.z + bb.z,
                                              (v.w - mean)*r*gg.w + bb.w);
    *(uint2*)(g_hb + (size_t)row*DMODEL + tx*4) =
        make_uint2(*(uint32_t*)&lo, *(uint32_t*)&hi);
}

/* ------------------------------------------------------------------ */
/* Transpose weight [K,N] fp32 -> [N,K] bf16.                         */
/* ------------------------------------------------------------------ */
__global__ void transpose_bf16_kernel(const float* __restrict__ W,
                                      __nv_bfloat16* __restrict__ Wt, int K, int N)
{
    __shared__ float tile[32][33];
    int n0 = blockIdx.x*32, k0 = blockIdx.y*32;
    int tx = threadIdx.x, ty = threadIdx.y;
    #pragma unroll
    for (int i = 0; i < 32; i += 8)
        tile[ty+i][tx] = W[(size_t)(k0+ty+i)*N + n0+tx];
    __syncthreads();
    #pragma unroll
    for (int i = 0; i < 32; i += 8)
        Wt[(size_t)(n0+ty+i)*K + k0+tx] = __float2bfloat16_rn(tile[tx][ty+i]);
}

/* ------------------------------------------------------------------ */
/* bf16 mma.sync GEMM, cp.async 3-stage (R5-proven config).           */
/* CTA 128x128, BK=32, 8 warps (warp tile 64x32), m16n8k16+ldmatrix.  */
/* MODE 0: bf16 store (silu applied when col0 >= gate_from)           */
/* MODE 1: rowsum += softplus(acc+bias)                               */
/* MODE 2: fp32 store C = acc + resid                                 */
/* ------------------------------------------------------------------ */
#define SROW 80                      /* bytes per smem row  */
#define TILEB (128*SROW)             /* 10240 B per operand */
#define STAGEB (2*TILEB)             /* A+B per stage       */
#define NSTG 3

#define CPASYNC16(dst, src) \
    asm volatile("cp.async.cg.shared.global [%0], [%1], 16;" :: "r"(dst), "l"(src))
#define CP_COMMIT() asm volatile("cp.async.commit_group;" ::: "memory")
#define CP_WAIT1()  asm volatile("cp.async.wait_group 1;" ::: "memory")

#define LDSM4(r0,r1,r2,r3, addr) \
    asm volatile("ldmatrix.sync.aligned.m8n8.x4.shared.b16 {%0,%1,%2,%3}, [%4];" \
        : "=r"(r0),"=r"(r1),"=r"(r2),"=r"(r3) : "r"(addr))

#define MMA_BF16(c, a, b0v, b1v) \
    asm volatile("mma.sync.aligned.m16n8k16.row.col.f32.bf16.bf16.f32 " \
        "{%0,%1,%2,%3},{%4,%5,%6,%7},{%8,%9},{%0,%1,%2,%3};" \
        : "+f"((c)[0]),"+f"((c)[1]),"+f"((c)[2]),"+f"((c)[3]) \
        : "r"((a)[0]),"r"((a)[1]),"r"((a)[2]),"r"((a)[3]), "r"(b0v),"r"(b1v))

__device__ __forceinline__ void stage_issue(uint32_t sbase, int stage,
                                            const __nv_bfloat16* Ab,
                                            const __nv_bfloat16* Bb,
                                            int Kd, int c, int tid)
{
    uint32_t sA = sbase + stage*STAGEB;
    uint32_t sB = sA + TILEB;
    int seg = tid & 3;
    int row = tid >> 2;                 /* 0..63 */
    #pragma unroll
    for (int i = 0; i < 2; i++) {
        int r = row + 64*i;
        CPASYNC16(sA + (uint32_t)(r*SROW + seg*16),
                  Ab + (size_t)r*Kd + c*32 + seg*8);
        CPASYNC16(sB + (uint32_t)(r*SROW + seg*16),
                  Bb + (size_t)r*Kd + c*32 + seg*8);
    }
}

template<int MODE>
__global__ __launch_bounds__(256, 2)
void mm_gemm_kernel(const __nv_bfloat16* __restrict__ A,
                    const __nv_bfloat16* __restrict__ Bt,
                    void* __restrict__ Cv, int M, int N, int Kd,
                    const float* __restrict__ bias,
                    float* __restrict__ rowsum,
                    const float* __restrict__ resid,
                    int gate_from)
{
    __shared__ __align__(16) unsigned char gsm[NSTG*STAGEB];
    uint32_t sbase = smem_u32(gsm);

    int tid  = threadIdx.x;
    int wid  = tid >> 5;
    int lane = tid & 31;
    int g    = lane >> 2;
    int q    = lane & 3;
    int mwb  = (wid & 1) * 64;
    int nwb  = (wid >> 1) * 32;
    int row0 = blockIdx.y * 128;
    int col0 = blockIdx.x * 128;

    const __nv_bfloat16* Ab = A  + (size_t)row0*Kd;
    const __nv_bfloat16* Bb = Bt + (size_t)col0*Kd;

    int r8 = lane & 7;
    uint32_t laneA = (uint32_t)((r8 + ((lane>>3)&1)*8)*SROW + ((lane>>4)&1)*16);
    uint32_t laneB = (uint32_t)((r8 + ((lane>>4)&1)*8)*SROW + ((lane>>3)&1)*16);

    float acc[4][4][4];
    #pragma unroll
    for (int mt = 0; mt < 4; mt++)
        #pragma unroll
        for (int nt = 0; nt < 4; nt++)
            #pragma unroll
            for (int j = 0; j < 4; j++) acc[mt][nt][j] = 0.f;

    const int nch = Kd >> 5;

    stage_issue(sbase, 0, Ab, Bb, Kd, 0, tid); CP_COMMIT();
    stage_issue(sbase, 1, Ab, Bb, Kd, 1, tid); CP_COMMIT();

    for (int c = 0; c < nch; c++) {
        CP_WAIT1();
        __syncthreads();
        if (c + 2 < nch)
            stage_issue(sbase, (c+2)%NSTG, Ab, Bb, Kd, c+2, tid);
        CP_COMMIT();

        uint32_t aBase = sbase + (c%NSTG)*STAGEB          + laneA;
        uint32_t bBase = sbase + (c%NSTG)*STAGEB + TILEB  + laneB;
        #pragma unroll
        for (int ks = 0; ks < 2; ks++) {
            uint32_t af[4][4], bf4[2][4];
            #pragma unroll
            for (int mt = 0; mt < 4; mt++)
                LDSM4(af[mt][0], af[mt][1], af[mt][2], af[mt][3],
                      aBase + (uint32_t)((mwb + mt*16)*SROW + ks*32));
            #pragma unroll
            for (int np = 0; np < 2; np++)
                LDSM4(bf4[np][0], bf4[np][1], bf4[np][2], bf4[np][3],
                      bBase + (uint32_t)((nwb + np*16)*SROW + ks*32));
            #pragma unroll
            for (int mt = 0; mt < 4; mt++)
                #pragma unroll
                for (int nt = 0; nt < 4; nt++)
                    MMA_BF16(acc[mt][nt], af[mt],
                             bf4[nt>>1][(nt&1)*2], bf4[nt>>1][(nt&1)*2+1]);
        }
    }
    __syncthreads();

    /* --------------------------- epilogue -------------------------- */
    if (MODE == 1) {
        float part[4][2];
        #pragma unroll
        for (int mt = 0; mt < 4; mt++) {
            float s0 = 0.f, s1 = 0.f;
            #pragma unroll
            for (int nt = 0; nt < 4; nt++) {
                int colb = col0 + nwb + nt*8 + 2*q;
                float b0 = bias[colb], b1 = bias[colb+1];
                float z;
                z = acc[mt][nt][0] + b0; s0 += (z > 20.f) ? z : log1pf(__expf(z));
                z = acc[mt][nt][1] + b1; s0 += (z > 20.f) ? z : log1pf(__expf(z));
                z = acc[mt][nt][2] + b0; s1 += (z > 20.f) ? z : log1pf(__expf(z));
                z = acc[mt][nt][3] + b1; s1 += (z > 20.f) ? z : log1pf(__expf(z));
            }
            part[mt][0] = s0; part[mt][1] = s1;
        }
        float* red = (float*)gsm;
        if (tid < 128) red[tid] = 0.f;
        __syncthreads();
        #pragma unroll
        for (int mt = 0; mt < 4; mt++) {
            atomicAdd(&red[mwb + mt*16 + g    ], part[mt][0]);
            atomicAdd(&red[mwb + mt*16 + g + 8], part[mt][1]);
        }
        __syncthreads();
        if (tid < 128)
            atomicAdd(&rowsum[row0 + tid], red[tid]);
    } else if (MODE == 0) {
        __nv_bfloat16* Cb = (__nv_bfloat16*)Cv;
        bool gate = (col0 >= gate_from);
        #pragma unroll
        for (int mt = 0; mt < 4; mt++) {
            int r0 = row0 + mwb + mt*16 + g;
            #pragma unroll
            for (int nt = 0; nt < 4; nt++) {
                int col = col0 + nwb + nt*8 + 2*q;
                float a0 = acc[mt][nt][0], a1 = acc[mt][nt][1];
                float a2 = acc[mt][nt][2], a3 = acc[mt][nt][3];
                if (gate) {
                    a0 = a0 / (1.f + __expf(-a0));
                    a1 = a1 / (1.f + __expf(-a1));
                    a2 = a2 / (1.f + __expf(-a2));
                    a3 = a3 / (1.f + __expf(-a3));
                }
                *(__nv_bfloat162*)(Cb + (size_t)r0*N + col) =
                    __floats2bfloat162_rn(a0, a1);
                *(__nv_bfloat162*)(Cb + (size_t)(r0+8)*N + col) =
                    __floats2bfloat162_rn(a2, a3);
            }
        }
    } else {
        float* C = (float*)Cv;
        #pragma unroll
        for (int mt = 0; mt < 4; mt++) {
            int r0 = row0 + mwb + mt*16 + g;
            #pragma unroll
            for (int nt = 0; nt < 4; nt++) {
                int col = col0 + nwb + nt*8 + 2*q;
                float2 o0 = make_float2(acc[mt][nt][0], acc[mt][nt][1]);
                float2 o1 = make_float2(acc[mt][nt][2], acc[mt][nt][3]);
                float2 rr0 = *(const float2*)(resid + (size_t)r0*N + col);
                float2 rr1 = *(const float2*)(resid + (size_t)(r0+8)*N + col);
                o0.x += rr0.x; o0.y += rr0.y;
                o1.x += rr1.x; o1.y += rr1.y;
                *(float2*)(C + (size_t)r0*N + col)     = o0;
                *(float2*)(C + (size_t)(r0+8)*N + col) = o1;
            }
        }
    }
}

/* ------------------------------------------------------------------ */
/* Depthwise causal conv (K=4) + bias + SiLU. bf16 in/out, 2 ch/thr.  */
/* CONV_CH=32 -> 512 blocks for occupancy.                            */
/* ------------------------------------------------------------------ */
#define CONV_CH 32
__global__ void conv_silu_kernel(const float* __restrict__ conv_w,
                                 const float* __restrict__ conv_b)
{
    int p  = blockIdx.x*256 + threadIdx.x;    /* pair 0..1023 */
    int d  = p*2;
    int b  = blockIdx.z;
    int l0 = blockIdx.y * CONV_CH;

    float4 wA = *(const float4*)(conv_w + d*4);
    float4 wB = *(const float4*)(conv_w + (d+1)*4);
    float cbA = conv_b[d], cbB = conv_b[d+1];

    const __nv_bfloat16* xg = g_xgb;
    float p1A=0.f,p2A=0.f,p3A=0.f, p1B=0.f,p2B=0.f,p3B=0.f;
    if (l0 >= 1) { __nv_bfloat162 t = *(const __nv_bfloat162*)(xg + ((size_t)(b*LSEQ+l0-1))*(2*DINNER) + d); p1A=__low2float(t); p1B=__high2float(t); }
    if (l0 >= 2) { __nv_bfloat162 t = *(const __nv_bfloat162*)(xg + ((size_t)(b*LSEQ+l0-2))*(2*DINNER) + d); p2A=__low2float(t); p2B=__high2float(t); }
    if (l0 >= 3) { __nv_bfloat162 t = *(const __nv_bfloat162*)(xg + ((size_t)(b*LSEQ+l0-3))*(2*DINNER) + d); p3A=__low2float(t); p3B=__high2float(t); }

    #pragma unroll 4
    for (int i = 0; i < CONV_CH; i++) {
        int l = l0 + i;
        __nv_bfloat162 t = *(const __nv_bfloat162*)(xg + ((size_t)(b*LSEQ+l))*(2*DINNER) + d);
        float cA = __low2float(t), cB = __high2float(t);
        float vA = wA.x*p3A + wA.y*p2A + wA.z*p1A + wA.w*cA + cbA;
        float vB = wB.x*p3B + wB.y*p2B + wB.z*p1B + wB.w*cB + cbB;
        float sA = vA / (1.f + __expf(-vA));
        float sB = vB / (1.f + __expf(-vB));
        *(__nv_bfloat162*)(g_xsb + ((size_t)(b*LSEQ+l))*DINNER + d) =
            __floats2bfloat162_rn(sA, sB);
        p3A = p2A; p2A = p1A; p1A = cA;
        p3B = p2B; p2B = p1B; p1B = cB;
    }
}

/* ------------------------------------------------------------------ */
/* Bx + dA: 8 rows per block (one warp per row), bf16 xs.             */
/* ------------------------------------------------------------------ */
__global__ void bxda_kernel(const float* __restrict__ B_mat,
                            const float* __restrict__ A_log)
{
    int row  = blockIdx.x*8 + (threadIdx.x >> 5);
    int lane = threadIdx.x & 31;

    float sums[NSTATE];
    #pragma unroll
    for (int n = 0; n < NSTATE; n++) sums[n] = 0.f;

    const __nv_bfloat16* xr = g_xsb + (size_t)row*DINNER;
    for (int pp = lane; pp < DINNER/2; pp += 32) {
        __nv_bfloat162 t = *(const __nv_bfloat162*)(xr + pp*2);
        float x0 = __low2float(t), x1 = __high2float(t);
        #pragma unroll
        for (int n = 0; n < NSTATE; n++) {
            float2 bm = *(const float2*)(B_mat + (size_t)n*DINNER + pp*2);
            sums[n] += x0*bm.x + x1*bm.y;
        }
    }
    #pragma unroll
    for (int n = 0; n < NSTATE; n++)
        #pragma unroll
        for (int o = 16; o; o >>= 1)
            sums[n] += __shfl_xor_sync(0xffffffffu, sums[n], o);

    if (lane < NSTATE) {
        float delta = g_delta[row] * (1.0f/DINNER);
        float An    = -__expf(A_log[lane]);
        g_Bx[row*NSTATE + lane] = sums[lane] * delta;
        g_dA[row*NSTATE + lane] = __expf(delta * An);
    }
}

/* ------------------------------------------------------------------ */
/* Parallel scan (Hillis-Steele over affine maps)                     */
/* ------------------------------------------------------------------ */
__global__ __launch_bounds__(1024)
void scan_kernel()
{
    __shared__ float Aa[2][LSEQ];
    __shared__ float Bb[2][LSEQ];
    int bn = blockIdx.x;
    int b  = bn >> 4;
    int n  = bn & 15;
    int tid = threadIdx.x;

    for (int l = tid; l < LSEQ; l += 1024) {
        size_t idx = ((size_t)(b*LSEQ + l))*NSTATE + n;
        Aa[0][l] = g_dA[idx];
        Bb[0][l] = g_Bx[idx];
    }
    __syncthreads();
    int src = 0;
    for (int off = 1; off < LSEQ; off <<= 1) {
        int dst = src ^ 1;
        for (int l = tid; l < LSEQ; l += 1024) {
            float a = Aa[src][l], bv = Bb[src][l];
            if (l >= off) {
                float ap = Aa[src][l-off], bp = Bb[src][l-off];
                Aa[dst][l] = a * ap;
                Bb[dst][l] = a * bp + bv;
            } else {
                Aa[dst][l] = a;
                Bb[dst][l] = bv;
            }
        }
        __syncthreads();
        src ^= 1;
    }
    for (int l = tid; l < LSEQ; l += 1024) {
        size_t idx = ((size_t)(b*LSEQ + l))*NSTATE + n;
        g_hs[idx] = Bb[src][l];
    }
}

/* ------------------------------------------------------------------ */
/* y = (hs @ C^T + D*xs) * gate   (gate pre-silu'd), bf16 out.        */
/* ------------------------------------------------------------------ */
__global__ void ymix_kernel(const float* __restrict__ C_mat,
                            const float* __restrict__ D_vec)
{
    int row = blockIdx.x;
    int tx  = threadIdx.x;      /* 256 */
    __shared__ float hrow[NSTATE];
    if (tx < NSTATE) hrow[tx] = g_hs[row*NSTATE + tx];
    __syncthreads();

    for (int pp = tx; pp < DINNER/2; pp += 256) {
        int d = pp*2;
        float acc0 = 0.f, acc1 = 0.f;
        const float4* c0 = (const float4*)(C_mat + (size_t)d*NSTATE);
        const float4* c1 = (const float4*)(C_mat + (size_t)(d+1)*NSTATE);
        #pragma unroll
        for (int qq = 0; qq < 4; qq++) {
            float4 ca = c0[qq], cb = c1[qq];
            acc0 += ca.x*hrow[qq*4+0] + ca.y*hrow[qq*4+1]
                  + ca.z*hrow[qq*4+2] + ca.w*hrow[qq*4+3];
            acc1 += cb.x*hrow[qq*4+0] + cb.y*hrow[qq*4+1]
                  + cb.z*hrow[qq*4+2] + cb.w*hrow[qq*4+3];
        }
        __nv_bfloat162 xt = *(const __nv_bfloat162*)(g_xsb + (size_t)row*DINNER + d);
        __nv_bfloat162 gt = *(const __nv_bfloat162*)(g_xgb + (size_t)row*(2*DINNER) + DINNER + d);
        float2 Dv = *(const float2*)(D_vec + d);
        float y0 = (acc0 + Dv.x*__low2float (xt)) * __low2float (gt);
        float y1 = (acc1 + Dv.y*__high2float(xt)) * __high2float(gt);
        *(__nv_bfloat162*)(g_yb + (size_t)row*DINNER + d) =
            __floats2bfloat162_rn(y0, y1);
    }
}

/* ------------------------------------------------------------------ */
extern "C" void kernel_launch(void* const* d_in, const int* in_sizes, int n_in,
                              void* d_out, int out_size)
{
    const float* x        = (const float*)d_in[0];
    const float* ln_gamma = (const float*)d_in[1];
    const float* ln_beta  = (const float*)d_in[2];
    const float* W_in     = (const float*)d_in[3];
    const float* conv_w   = (const float*)d_in[4];
    const float* conv_b   = (const float*)d_in[5];
    const float* A_log    = (const float*)d_in[6];
    const float* B_mat    = (const float*)d_in[7];
    const float* C_mat    = (const float*)d_in[8];
    const float* D_vec    = (const float*)d_in[9];
    const float* Wd       = (const float*)d_in[10];
    const float* bd       = (const float*)d_in[11];
    const float* W_out    = (const float*)d_in[12];
    float* out = (float*)d_out;

    float *p_delta;
    __nv_bfloat16 *p_hb, *p_xgb, *p_xsb, *p_yb, *p_wt;
    cudaGetSymbolAddress((void**)&p_hb,    g_hb);
    cudaGetSymbolAddress((void**)&p_xgb,   g_xgb);
    cudaGetSymbolAddress((void**)&p_xsb,   g_xsb);
    cudaGetSymbolAddress((void**)&p_delta, g_delta);
    cudaGetSymbolAddress((void**)&p_yb,    g_yb);
    cudaGetSymbolAddress((void**)&p_wt,    g_wt);

    /* 1. LayerNorm (bf16 out) + delta zero */
    ln_kernel<<<ROWS, 256>>>(x, ln_gamma, ln_beta);

    /* 2. W_in^T, then xg = h @ W_in  (gate half gets silu, bf16) */
    transpose_bf16_kernel<<<dim3((2*DINNER)/32, DMODEL/32), dim3(32,8)>>>(
        W_in, p_wt, DMODEL, 2*DINNER);
    mm_gemm_kernel<0><<<dim3((2*DINNER)/128, ROWS/128), 256>>>(
        p_hb, p_wt, p_xgb, ROWS, 2*DINNER, DMODEL,
        nullptr, nullptr, nullptr, DINNER);

    /* 3. depthwise causal conv + SiLU (bf16) */
    conv_silu_kernel<<<dim3(DINNER/512, LSEQ/CONV_CH, BSZ), 256>>>(conv_w, conv_b);

    /* 4. Wd^T, then delta row-sums = sum softplus(xs @ Wd + bd) */
    transpose_bf16_kernel<<<dim3(DINNER/32, DINNER/32), dim3(32,8)>>>(
        Wd, p_wt, DINNER, DINNER);
    mm_gemm_kernel<1><<<dim3(DINNER/128, ROWS/128), 256>>>(
        p_xsb, p_wt, nullptr, ROWS, DINNER, DINNER,
        bd, p_delta, nullptr, 1<<30);

    /* 5. Bx, dA */
    bxda_kernel<<<ROWS/8, 256>>>(B_mat, A_log);

    /* 6. scan over L */
    scan_kernel<<<BSZ*NSTATE, 1024>>>();

    /* 7. y = (hs @ C^T + D*xs) * gate  (bf16 out) */
    ymix_kernel<<<ROWS, 256>>>(C_mat, D_vec);

    /* 8. W_out^T, then out = y @ W_out + x */
    transpose_bf16_kernel<<<dim3(DMODEL/32, DINNER/32), dim3(32,8)>>>(
        W_out, p_wt, DINNER, DMODEL);
    mm_gemm_kernel<2><<<dim3(DMODEL/128, ROWS/128), 256>>>(
        p_yb, p_wt, out, ROWS, DMODEL, DINNER,
        nullptr, nullptr, x, 1<<30);
}

// round 10
// speedup vs baseline: 1.0914x; 1.0351x over previous
#include <cuda_runtime.h>
#include <cuda_bf16.h>
#include <math.h>
#include <stdint.h>

#define BSZ 2
#define LSEQ 2048
#define DMODEL 1024
#define DINNER 2048
#define NSTATE 16
#define ROWS (BSZ*LSEQ)   /* 4096 */

/* ------------------------------------------------------------------ */
/* Scratch (bf16 intermediates; every bf16 path feeds a >=2048-length */
/* averaged reduction before the output)                              */
/* ------------------------------------------------------------------ */
__device__ __nv_bfloat16 g_hb [(size_t)ROWS*DMODEL];    /* post-LN          */
__device__ __nv_bfloat16 g_xgb[(size_t)ROWS*2*DINNER];  /* xs_raw | silu(gate) */
__device__ __nv_bfloat16 g_xsb[(size_t)ROWS*DINNER];    /* conv+silu        */
__device__ float g_delta[ROWS];
__device__ float g_dA  [(size_t)ROWS*NSTATE];
__device__ float g_Bx  [(size_t)ROWS*NSTATE];
__device__ float g_hs  [(size_t)ROWS*NSTATE];
__device__ __nv_bfloat16 g_yb [(size_t)ROWS*DINNER];    /* pre-W_out        */
__device__ __nv_bfloat16 g_wt [(size_t)4096*2048];      /* transposed W     */

__device__ __forceinline__ uint32_t smem_u32(const void* p) {
    uint32_t a;
    asm("{ .reg .u64 t; cvta.to.shared.u64 t, %1; cvt.u32.u64 %0, t; }" : "=r"(a) : "l"(p));
    return a;
}

/* ------------------------------------------------------------------ */
/* LayerNorm (+ zero delta): one block per row of 1024                */
/* ------------------------------------------------------------------ */
__global__ void ln_kernel(const float* __restrict__ x,
                          const float* __restrict__ gamma,
                          const float* __restrict__ beta)
{
    int row = blockIdx.x;
    int tx  = threadIdx.x;                       /* 256 threads */
    if (tx == 0) g_delta[row] = 0.f;
    const float4* xr = (const float4*)(x + (size_t)row*DMODEL);
    float4 v = xr[tx];
    float s  = v.x + v.y + v.z + v.w;
    float ss = v.x*v.x + v.y*v.y + v.z*v.z + v.w*v.w;
    #pragma unroll
    for (int o = 16; o; o >>= 1) {
        s  += __shfl_down_sync(0xffffffffu, s,  o);
        ss += __shfl_down_sync(0xffffffffu, ss, o);
    }
    __shared__ float sh[8], sh2[8];
    int w = tx >> 5, l = tx & 31;
    if (l == 0) { sh[w] = s; sh2[w] = ss; }
    __syncthreads();
    if (tx == 0) {
        float S = 0.f, SS = 0.f;
        #pragma unroll
        for (int i = 0; i < 8; i++) { S += sh[i]; SS += sh2[i]; }
        sh[0]  = S  * (1.0f/DMODEL);
        sh2[0] = SS * (1.0f/DMODEL);
    }
    __syncthreads();
    float mean = sh[0];
    float var  = sh2[0] - mean*mean;
    float r    = rsqrtf(var + 1e-5f);
    float4 gg = ((const float4*)gamma)[tx];
    float4 bb = ((const float4*)beta )[tx];
    __nv_bfloat162 lo = __floats2bfloat162_rn((v.x - mean)*r*gg.x + bb.x,
                                              (v.y - mean)*r*gg.y + bb.y);
    __nv_bfloat162 hi = __floats2bfloat162_rn((v.z - mean)*r*gg.z + bb.z,
                                              (v.w - mean)*r*gg.w + bb.w);
    *(uint2*)(g_hb + (size_t)row*DMODEL + tx*4) =
        make_uint2(*(uint32_t*)&lo, *(uint32_t*)&hi);
}

/* ------------------------------------------------------------------ */
/* Transpose weight [K,N] fp32 -> [N,K] bf16.                         */
/* ------------------------------------------------------------------ */
__global__ void transpose_bf16_kernel(const float* __restrict__ W,
                                      __nv_bfloat16* __restrict__ Wt, int K, int N)
{
    __shared__ float tile[32][33];
    int n0 = blockIdx.x*32, k0 = blockIdx.y*32;
    int tx = threadIdx.x, ty = threadIdx.y;
    #pragma unroll
    for (int i = 0; i < 32; i += 8)
        tile[ty+i][tx] = W[(size_t)(k0+ty+i)*N + n0+tx];
    __syncthreads();
    #pragma unroll
    for (int i = 0; i < 32; i += 8)
        Wt[(size_t)(n0+ty+i)*K + k0+tx] = __float2bfloat16_rn(tile[tx][ty+i]);
}

/* ------------------------------------------------------------------ */
/* bf16 mma.sync GEMM, cp.async 3-stage, BK=64 (half the sync walls). */
/* CTA 128x128, 8 warps (warp tile 64x32), m16n8k16 + ldmatrix.       */
/* SROW=144B: row stride 36 ints -> ldmatrix banks (36r+4s)%32 all    */
/* distinct -> conflict-free.                                         */
/* MODE 0: bf16 store (silu applied when col0 >= gate_from)           */
/* MODE 1: rowsum += softplus(acc+bias)                               */
/* MODE 2: fp32 store C = acc + resid                                 */
/* ------------------------------------------------------------------ */
#define SROW 144                     /* bytes per smem row (128 data + 16 pad) */
#define TILEB (128*SROW)             /* 18432 B per operand */
#define STAGEB (2*TILEB)             /* A+B per stage       */
#define NSTG 3
#define GSMEM (NSTG*STAGEB)          /* 110592 B            */

#define CPASYNC16(dst, src) \
    asm volatile("cp.async.cg.shared.global [%0], [%1], 16;" :: "r"(dst), "l"(src))
#define CP_COMMIT() asm volatile("cp.async.commit_group;" ::: "memory")
#define CP_WAIT1()  asm volatile("cp.async.wait_group 1;" ::: "memory")

#define LDSM4(r0,r1,r2,r3, addr) \
    asm volatile("ldmatrix.sync.aligned.m8n8.x4.shared.b16 {%0,%1,%2,%3}, [%4];" \
        : "=r"(r0),"=r"(r1),"=r"(r2),"=r"(r3) : "r"(addr))

#define MMA_BF16(c, a, b0v, b1v) \
    asm volatile("mma.sync.aligned.m16n8k16.row.col.f32.bf16.bf16.f32 " \
        "{%0,%1,%2,%3},{%4,%5,%6,%7},{%8,%9},{%0,%1,%2,%3};" \
        : "+f"((c)[0]),"+f"((c)[1]),"+f"((c)[2]),"+f"((c)[3]) \
        : "r"((a)[0]),"r"((a)[1]),"r"((a)[2]),"r"((a)[3]), "r"(b0v),"r"(b1v))

__device__ __forceinline__ void stage_issue(uint32_t sbase, int stage,
                                            const __nv_bfloat16* Ab,
                                            const __nv_bfloat16* Bb,
                                            int Kd, int c, int tid)
{
    uint32_t sA = sbase + stage*STAGEB;
    uint32_t sB = sA + TILEB;
    int seg = tid & 7;                  /* 16B unit within 128B row */
    int row = tid >> 3;                 /* 0..31 */
    #pragma unroll
    for (int i = 0; i < 4; i++) {
        int r = row + 32*i;
        CPASYNC16(sA + (uint32_t)(r*SROW + seg*16),
                  Ab + (size_t)r*Kd + c*64 + seg*8);
        CPASYNC16(sB + (uint32_t)(r*SROW + seg*16),
                  Bb + (size_t)r*Kd + c*64 + seg*8);
    }
}

template<int MODE>
__global__ __launch_bounds__(256, 2)
void mm_gemm_kernel(const __nv_bfloat16* __restrict__ A,
                    const __nv_bfloat16* __restrict__ Bt,
                    void* __restrict__ Cv, int M, int N, int Kd,
                    const float* __restrict__ bias,
                    float* __restrict__ rowsum,
                    const float* __restrict__ resid,
                    int gate_from)
{
    extern __shared__ __align__(16) unsigned char gsm[];
    uint32_t sbase = smem_u32(gsm);

    int tid  = threadIdx.x;
    int wid  = tid >> 5;
    int lane = tid & 31;
    int g    = lane >> 2;
    int q    = lane & 3;
    int mwb  = (wid & 1) * 64;
    int nwb  = (wid >> 1) * 32;
    int row0 = blockIdx.y * 128;
    int col0 = blockIdx.x * 128;

    const __nv_bfloat16* Ab = A  + (size_t)row0*Kd;
    const __nv_bfloat16* Bb = Bt + (size_t)col0*Kd;

    int r8 = lane & 7;
    uint32_t laneA = (uint32_t)((r8 + ((lane>>3)&1)*8)*SROW + ((lane>>4)&1)*16);
    uint32_t laneB = (uint32_t)((r8 + ((lane>>4)&1)*8)*SROW + ((lane>>3)&1)*16);

    float acc[4][4][4];
    #pragma unroll
    for (int mt = 0; mt < 4; mt++)
        #pragma unroll
        for (int nt = 0; nt < 4; nt++)
            #pragma unroll
            for (int j = 0; j < 4; j++) acc[mt][nt][j] = 0.f;

    const int nch = Kd >> 6;            /* BK=64 chunks */

    stage_issue(sbase, 0, Ab, Bb, Kd, 0, tid); CP_COMMIT();
    stage_issue(sbase, 1, Ab, Bb, Kd, 1, tid); CP_COMMIT();

    for (int c = 0; c < nch; c++) {
        CP_WAIT1();
        __syncthreads();
        if (c + 2 < nch)
            stage_issue(sbase, (c+2)%NSTG, Ab, Bb, Kd, c+2, tid);
        CP_COMMIT();

        uint32_t aBase = sbase + (c%NSTG)*STAGEB          + laneA;
        uint32_t bBase = sbase + (c%NSTG)*STAGEB + TILEB  + laneB;
        #pragma unroll
        for (int ks = 0; ks < 4; ks++) {   /* 4 k16 steps per BK=64 */
            uint32_t af[4][4], bf4[2][4];
            #pragma unroll
            for (int mt = 0; mt < 4; mt++)
                LDSM4(af[mt][0], af[mt][1], af[mt][2], af[mt][3],
                      aBase + (uint32_t)((mwb + mt*16)*SROW + ks*32));
            #pragma unroll
            for (int np = 0; np < 2; np++)
                LDSM4(bf4[np][0], bf4[np][1], bf4[np][2], bf4[np][3],
                      bBase + (uint32_t)((nwb + np*16)*SROW + ks*32));
            #pragma unroll
            for (int mt = 0; mt < 4; mt++)
                #pragma unroll
                for (int nt = 0; nt < 4; nt++)
                    MMA_BF16(acc[mt][nt], af[mt],
                             bf4[nt>>1][(nt&1)*2], bf4[nt>>1][(nt&1)*2+1]);
        }
    }
    __syncthreads();

    /* --------------------------- epilogue -------------------------- */
    if (MODE == 1) {
        float part[4][2];
        #pragma unroll
        for (int mt = 0; mt < 4; mt++) {
            float s0 = 0.f, s1 = 0.f;
            #pragma unroll
            for (int nt = 0; nt < 4; nt++) {
                int colb = col0 + nwb + nt*8 + 2*q;
                float b0 = bias[colb], b1 = bias[colb+1];
                float z;
                z = acc[mt][nt][0] + b0; s0 += (z > 20.f) ? z : log1pf(__expf(z));
                z = acc[mt][nt][1] + b1; s0 += (z > 20.f) ? z : log1pf(__expf(z));
                z = acc[mt][nt][2] + b0; s1 += (z > 20.f) ? z : log1pf(__expf(z));
                z = acc[mt][nt][3] + b1; s1 += (z > 20.f) ? z : log1pf(__expf(z));
            }
            part[mt][0] = s0; part[mt][1] = s1;
        }
        float* red = (float*)gsm;
        if (tid < 128) red[tid] = 0.f;
        __syncthreads();
        #pragma unroll
        for (int mt = 0; mt < 4; mt++) {
            atomicAdd(&red[mwb + mt*16 + g    ], part[mt][0]);
            atomicAdd(&red[mwb + mt*16 + g + 8], part[mt][1]);
        }
        __syncthreads();
        if (tid < 128)
            atomicAdd(&rowsum[row0 + tid], red[tid]);
    } else if (MODE == 0) {
        __nv_bfloat16* Cb = (__nv_bfloat16*)Cv;
        bool gate = (col0 >= gate_from);
        #pragma unroll
        for (int mt = 0; mt < 4; mt++) {
            int r0 = row0 + mwb + mt*16 + g;
            #pragma unroll
            for (int nt = 0; nt < 4; nt++) {
                int col = col0 + nwb + nt*8 + 2*q;
                float a0 = acc[mt][nt][0], a1 = acc[mt][nt][1];
                float a2 = acc[mt][nt][2], a3 = acc[mt][nt][3];
                if (gate) {
                    a0 = a0 / (1.f + __expf(-a0));
                    a1 = a1 / (1.f + __expf(-a1));
                    a2 = a2 / (1.f + __expf(-a2));
                    a3 = a3 / (1.f + __expf(-a3));
                }
                *(__nv_bfloat162*)(Cb + (size_t)r0*N + col) =
                    __floats2bfloat162_rn(a0, a1);
                *(__nv_bfloat162*)(Cb + (size_t)(r0+8)*N + col) =
                    __floats2bfloat162_rn(a2, a3);
            }
        }
    } else {
        float* C = (float*)Cv;
        #pragma unroll
        for (int mt = 0; mt < 4; mt++) {
            int r0 = row0 + mwb + mt*16 + g;
            #pragma unroll
            for (int nt = 0; nt < 4; nt++) {
                int col = col0 + nwb + nt*8 + 2*q;
                float2 o0 = make_float2(acc[mt][nt][0], acc[mt][nt][1]);
                float2 o1 = make_float2(acc[mt][nt][2], acc[mt][nt][3]);
                float2 rr0 = *(const float2*)(resid + (size_t)r0*N + col);
                float2 rr1 = *(const float2*)(resid + (size_t)(r0+8)*N + col);
                o0.x += rr0.x; o0.y += rr0.y;
                o1.x += rr1.x; o1.y += rr1.y;
                *(float2*)(C + (size_t)r0*N + col)     = o0;
                *(float2*)(C + (size_t)(r0+8)*N + col) = o1;
            }
        }
    }
}

/* ------------------------------------------------------------------ */
/* Depthwise causal conv (K=4) + bias + SiLU. bf16 in/out, 2 ch/thr.  */
/* ------------------------------------------------------------------ */
#define CONV_CH 32
__global__ void conv_silu_kernel(const float* __restrict__ conv_w,
                                 const float* __restrict__ conv_b)
{
    int p  = blockIdx.x*256 + threadIdx.x;    /* pair 0..1023 */
    int d  = p*2;
    int b  = blockIdx.z;
    int l0 = blockIdx.y * CONV_CH;

    float4 wA = *(const float4*)(conv_w + d*4);
    float4 wB = *(const float4*)(conv_w + (d+1)*4);
    float cbA = conv_b[d], cbB = conv_b[d+1];

    const __nv_bfloat16* xg = g_xgb;
    float p1A=0.f,p2A=0.f,p3A=0.f, p1B=0.f,p2B=0.f,p3B=0.f;
    if (l0 >= 1) { __nv_bfloat162 t = *(const __nv_bfloat162*)(xg + ((size_t)(b*LSEQ+l0-1))*(2*DINNER) + d); p1A=__low2float(t); p1B=__high2float(t); }
    if (l0 >= 2) { __nv_bfloat162 t = *(const __nv_bfloat162*)(xg + ((size_t)(b*LSEQ+l0-2))*(2*DINNER) + d); p2A=__low2float(t); p2B=__high2float(t); }
    if (l0 >= 3) { __nv_bfloat162 t = *(const __nv_bfloat162*)(xg + ((size_t)(b*LSEQ+l0-3))*(2*DINNER) + d); p3A=__low2float(t); p3B=__high2float(t); }

    #pragma unroll 4
    for (int i = 0; i < CONV_CH; i++) {
        int l = l0 + i;
        __nv_bfloat162 t = *(const __nv_bfloat162*)(xg + ((size_t)(b*LSEQ+l))*(2*DINNER) + d);
        float cA = __low2float(t), cB = __high2float(t);
        float vA = wA.x*p3A + wA.y*p2A + wA.z*p1A + wA.w*cA + cbA;
        float vB = wB.x*p3B + wB.y*p2B + wB.z*p1B + wB.w*cB + cbB;
        float sA = vA / (1.f + __expf(-vA));
        float sB = vB / (1.f + __expf(-vB));
        *(__nv_bfloat162*)(g_xsb + ((size_t)(b*LSEQ+l))*DINNER + d) =
            __floats2bfloat162_rn(sA, sB);
        p3A = p2A; p2A = p1A; p1A = cA;
        p3B = p2B; p2B = p1B; p1B = cB;
    }
}

/* ------------------------------------------------------------------ */
/* Bx + dA: 8 rows per block (one warp per row), bf16 xs.             */
/* ------------------------------------------------------------------ */
__global__ void bxda_kernel(const float* __restrict__ B_mat,
                            const float* __restrict__ A_log)
{
    int row  = blockIdx.x*8 + (threadIdx.x >> 5);
    int lane = threadIdx.x & 31;

    float sums[NSTATE];
    #pragma unroll
    for (int n = 0; n < NSTATE; n++) sums[n] = 0.f;

    const __nv_bfloat16* xr = g_xsb + (size_t)row*DINNER;
    for (int pp = lane; pp < DINNER/2; pp += 32) {
        __nv_bfloat162 t = *(const __nv_bfloat162*)(xr + pp*2);
        float x0 = __low2float(t), x1 = __high2float(t);
        #pragma unroll
        for (int n = 0; n < NSTATE; n++) {
            float2 bm = *(const float2*)(B_mat + (size_t)n*DINNER + pp*2);
            sums[n] += x0*bm.x + x1*bm.y;
        }
    }
    #pragma unroll
    for (int n = 0; n < NSTATE; n++)
        #pragma unroll
        for (int o = 16; o; o >>= 1)
            sums[n] += __shfl_xor_sync(0xffffffffu, sums[n], o);

    if (lane < NSTATE) {
        float delta = g_delta[row] * (1.0f/DINNER);
        float An    = -__expf(A_log[lane]);
        g_Bx[row*NSTATE + lane] = sums[lane] * delta;
        g_dA[row*NSTATE + lane] = __expf(delta * An);
    }
}

/* ------------------------------------------------------------------ */
/* Parallel scan (Hillis-Steele over affine maps)                     */
/* ------------------------------------------------------------------ */
__global__ __launch_bounds__(1024)
void scan_kernel()
{
    __shared__ float Aa[2][LSEQ];
    __shared__ float Bb[2][LSEQ];
    int bn = blockIdx.x;
    int b  = bn >> 4;
    int n  = bn & 15;
    int tid = threadIdx.x;

    for (int l = tid; l < LSEQ; l += 1024) {
        size_t idx = ((size_t)(b*LSEQ + l))*NSTATE + n;
        Aa[0][l] = g_dA[idx];
        Bb[0][l] = g_Bx[idx];
    }
    __syncthreads();
    int src = 0;
    for (int off = 1; off < LSEQ; off <<= 1) {
        int dst = src ^ 1;
        for (int l = tid; l < LSEQ; l += 1024) {
            float a = Aa[src][l], bv = Bb[src][l];
            if (l >= off) {
                float ap = Aa[src][l-off], bp = Bb[src][l-off];
                Aa[dst][l] = a * ap;
                Bb[dst][l] = a * bp + bv;
            } else {
                Aa[dst][l] = a;
                Bb[dst][l] = bv;
            }
        }
        __syncthreads();
        src ^= 1;
    }
    for (int l = tid; l < LSEQ; l += 1024) {
        size_t idx = ((size_t)(b*LSEQ + l))*NSTATE + n;
        g_hs[idx] = Bb[src][l];
    }
}

/* ------------------------------------------------------------------ */
/* y = (hs @ C^T + D*xs) * gate   (gate pre-silu'd), bf16 out.        */
/* ------------------------------------------------------------------ */
__global__ void ymix_kernel(const float* __restrict__ C_mat,
                            const float* __restrict__ D_vec)
{
    int row = blockIdx.x;
    int tx  = threadIdx.x;      /* 256 */
    __shared__ float hrow[NSTATE];
    if (tx < NSTATE) hrow[tx] = g_hs[row*NSTATE + tx];
    __syncthreads();

    for (int pp = tx; pp < DINNER/2; pp += 256) {
        int d = pp*2;
        float acc0 = 0.f, acc1 = 0.f;
        const float4* c0 = (const float4*)(C_mat + (size_t)d*NSTATE);
        const float4* c1 = (const float4*)(C_mat + (size_t)(d+1)*NSTATE);
        #pragma unroll
        for (int qq = 0; qq < 4; qq++) {
            float4 ca = c0[qq], cb = c1[qq];
            acc0 += ca.x*hrow[qq*4+0] + ca.y*hrow[qq*4+1]
                  + ca.z*hrow[qq*4+2] + ca.w*hrow[qq*4+3];
            acc1 += cb.x*hrow[qq*4+0] + cb.y*hrow[qq*4+1]
                  + cb.z*hrow[qq*4+2] + cb.w*hrow[qq*4+3];
        }
        __nv_bfloat162 xt = *(const __nv_bfloat162*)(g_xsb + (size_t)row*DINNER + d);
        __nv_bfloat162 gt = *(const __nv_bfloat162*)(g_xgb + (size_t)row*(2*DINNER) + DINNER + d);
        float2 Dv = *(const float2*)(D_vec + d);
        float y0 = (acc0 + Dv.x*__low2float (xt)) * __low2float (gt);
        float y1 = (acc1 + Dv.y*__high2float(xt)) * __high2float(gt);
        *(__nv_bfloat162*)(g_yb + (size_t)row*DINNER + d) =
            __floats2bfloat162_rn(y0, y1);
    }
}

/* ------------------------------------------------------------------ */
extern "C" void kernel_launch(void* const* d_in, const int* in_sizes, int n_in,
                              void* d_out, int out_size)
{
    const float* x        = (const float*)d_in[0];
    const float* ln_gamma = (const float*)d_in[1];
    const float* ln_beta  = (const float*)d_in[2];
    const float* W_in     = (const float*)d_in[3];
    const float* conv_w   = (const float*)d_in[4];
    const float* conv_b   = (const float*)d_in[5];
    const float* A_log    = (const float*)d_in[6];
    const float* B_mat    = (const float*)d_in[7];
    const float* C_mat    = (const float*)d_in[8];
    const float* D_vec    = (const float*)d_in[9];
    const float* Wd       = (const float*)d_in[10];
    const float* bd       = (const float*)d_in[11];
    const float* W_out    = (const float*)d_in[12];
    float* out = (float*)d_out;

    float *p_delta;
    __nv_bfloat16 *p_hb, *p_xgb, *p_xsb, *p_yb, *p_wt;
    cudaGetSymbolAddress((void**)&p_hb,    g_hb);
    cudaGetSymbolAddress((void**)&p_xgb,   g_xgb);
    cudaGetSymbolAddress((void**)&p_xsb,   g_xsb);
    cudaGetSymbolAddress((void**)&p_delta, g_delta);
    cudaGetSymbolAddress((void**)&p_yb,    g_yb);
    cudaGetSymbolAddress((void**)&p_wt,    g_wt);

    cudaFuncSetAttribute((const void*)mm_gemm_kernel<0>,
        cudaFuncAttributeMaxDynamicSharedMemorySize, GSMEM);
    cudaFuncSetAttribute((const void*)mm_gemm_kernel<1>,
        cudaFuncAttributeMaxDynamicSharedMemorySize, GSMEM);
    cudaFuncSetAttribute((const void*)mm_gemm_kernel<2>,
        cudaFuncAttributeMaxDynamicSharedMemorySize, GSMEM);

    /* 1. LayerNorm (bf16 out) + delta zero */
    ln_kernel<<<ROWS, 256>>>(x, ln_gamma, ln_beta);

    /* 2. W_in^T, then xg = h @ W_in  (gate half gets silu, bf16) */
    transpose_bf16_kernel<<<dim3((2*DINNER)/32, DMODEL/32), dim3(32,8)>>>(
        W_in, p_wt, DMODEL, 2*DINNER);
    mm_gemm_kernel<0><<<dim3((2*DINNER)/128, ROWS/128), 256, GSMEM>>>(
        p_hb, p_wt, p_xgb, ROWS, 2*DINNER, DMODEL,
        nullptr, nullptr, nullptr, DINNER);

    /* 3. depthwise causal conv + SiLU (bf16) */
    conv_silu_kernel<<<dim3(DINNER/512, LSEQ/CONV_CH, BSZ), 256>>>(conv_w, conv_b);

    /* 4. Wd^T, then delta row-sums = sum softplus(xs @ Wd + bd) */
    transpose_bf16_kernel<<<dim3(DINNER/32, DINNER/32), dim3(32,8)>>>(
        Wd, p_wt, DINNER, DINNER);
    mm_gemm_kernel<1><<<dim3(DINNER/128, ROWS/128), 256, GSMEM>>>(
        p_xsb, p_wt, nullptr, ROWS, DINNER, DINNER,
        bd, p_delta, nullptr, 1<<30);

    /* 5. Bx, dA */
    bxda_kernel<<<ROWS/8, 256>>>(B_mat, A_log);

    /* 6. scan over L */
    scan_kernel<<<BSZ*NSTATE, 1024>>>();

    /* 7. y = (hs @ C^T + D*xs) * gate  (bf16 out) */
    ymix_kernel<<<ROWS, 256>>>(C_mat, D_vec);

    /* 8. W_out^T, then out = y @ W_out + x */
    transpose_bf16_kernel<<<dim3(DMODEL/32, DINNER/32), dim3(32,8)>>>(
        W_out, p_wt, DINNER, DMODEL);
    mm_gemm_kernel<2><<<dim3(DMODEL/128, ROWS/128), 256, GSMEM>>>(
        p_yb, p_wt, out, ROWS, DMODEL, DINNER,
        nullptr, nullptr, x, 1<<30);
}